// round 5
// baseline (speedup 1.0000x reference)
#include <cuda_runtime.h>
#include <math.h>

#define B 128
#define T 2048
#define D 64
#define H 128
#define O 32
#define XTILE 8
#define NTH 768      // 24 warps: A = w0-7 (rec0 + FC bursts), C = w8-23 (fused proj1+rec1)

// arena layout (float offsets)
#define OFF_H1   0              // h1 ring: 2 x 128
#define OFF_H2   264            // h2 history: 32 x 128
#define OFF_XS   4360           // xp0 tiles: 2 x 8 x 128
#define OFF_WFC  6408           // Wfc staged, padded rows: 32 x 132
#define OFF_BFC  10632          // b_fc: 32
#define ARENA_F  10664          // 42656 B < 48KB static limit

__device__ float g_s0[(size_t)B * T * H];   // xp0 scratch

// ---------------------------------------------------------------------------
// helpers
// ---------------------------------------------------------------------------
__device__ __forceinline__ unsigned long long ffma2(unsigned long long a,
                                                    unsigned long long b,
                                                    unsigned long long c) {
    unsigned long long d;
    asm("fma.rn.f32x2 %0, %1, %2, %3;" : "=l"(d) : "l"(a), "l"(b), "l"(c));
    return d;
}
__device__ __forceinline__ unsigned long long addf2(unsigned long long a,
                                                    unsigned long long b) {
    unsigned long long d;
    asm("add.rn.f32x2 %0, %1, %2;" : "=l"(d) : "l"(a), "l"(b));
    return d;
}
__device__ __forceinline__ float f2lo(unsigned long long v) {
    return __uint_as_float((unsigned)(v & 0xffffffffull));
}
__device__ __forceinline__ float f2hi(unsigned long long v) {
    return __uint_as_float((unsigned)(v >> 32));
}
__device__ __forceinline__ float tanh_fast(float x) {
    float y;
    asm("tanh.approx.f32 %0, %1;" : "=f"(y) : "f"(x));
    return y;
}
__device__ __forceinline__ void cp16(const float* smem_f, const float* g) {
    unsigned s = (unsigned)__cvta_generic_to_shared(smem_f);
    asm volatile("cp.async.cg.shared.global [%0], [%1], 16;" :: "r"(s), "l"(g));
}
#define CP_COMMIT() asm volatile("cp.async.commit_group;")
#define CP_WAIT1()  asm volatile("cp.async.wait_group 1;")

// ---------------------------------------------------------------------------
// Input projection (layer 0): xp0[b,t,j] = x[b,t,:]·W_ih0[j,:] + b_ih0 + b_hh0
// ---------------------------------------------------------------------------
template <int K>
__global__ __launch_bounds__(128) void proj_kernel(
    const float* __restrict__ in, float* __restrict__ out,
    const float* __restrict__ W, const float* __restrict__ b1,
    const float* __restrict__ b2, const int* __restrict__ lengths)
{
    constexpr int CT = 16;
    const int b  = blockIdx.y;
    const int t0 = blockIdx.x * CT;
    const int len = lengths[b];
    if (t0 >= len) return;

    const int j = threadIdx.x;
    __shared__ __align__(16) float xs[CT][K];

    unsigned long long wq[K / 2];
    {
        const ulonglong2* Wp = (const ulonglong2*)(W + (size_t)j * K);
#pragma unroll
        for (int i = 0; i < K / 4; ++i) {
            ulonglong2 v = Wp[i];
            wq[2 * i] = v.x; wq[2 * i + 1] = v.y;
        }
    }
    const float bias = b1[j] + b2[j];

    const int nt = min(CT, len - t0);
    const float* inp = in + ((size_t)b * T + t0) * K;
    for (int idx = j; idx < nt * K / 4; idx += 128)
        ((float4*)xs)[idx] = ((const float4*)inp)[idx];
    __syncthreads();

    for (int tt = 0; tt < nt; ++tt) {
        unsigned long long a0 = 0ull, a1 = 0ull;
        const ulonglong2* xr = (const ulonglong2*)&xs[tt][0];
#pragma unroll
        for (int i = 0; i < K / 4; ++i) {
            ulonglong2 hv = xr[i];
            a0 = ffma2(wq[2 * i], hv.x, a0);
            a1 = ffma2(wq[2 * i + 1], hv.y, a1);
        }
        unsigned long long a = addf2(a0, a1);
        out[((size_t)b * T + t0 + tt) * H + j] = bias + f2lo(a) + f2hi(a);
    }
}

// ---------------------------------------------------------------------------
// FC tile: out[b, t, o] for t in [s0, s1] (<=16 steps), run on A warps.
// Warp w handles t = s0+2w, s0+2w+1; lane = o. Weights from padded smem.
// NOTE: one lane computes the FULL dot -> must walk all 32 16B chunks
// (k = 4c .. 4c+3, c = 0..31).
// ---------------------------------------------------------------------------
__device__ __forceinline__ void fc_tile(const float* __restrict__ arena,
                                        float* __restrict__ obase,
                                        int s0, int s1, int w, int lane)
{
    const int o = lane;
    const float* wr = arena + OFF_WFC + o * 132;
#pragma unroll
    for (int c2 = 0; c2 < 2; ++c2) {
        int t = s0 + 2 * w + c2;
        if (t <= s1) {
            const float* hr = arena + OFF_H2 + (t & 31) * 128;
            unsigned long long a0 = 0ull, a1 = 0ull;
#pragma unroll
            for (int c = 0; c < 32; ++c) {
                ulonglong2 wv = *(const ulonglong2*)(wr + 4 * c);
                ulonglong2 hv = *(const ulonglong2*)(hr + 4 * c);
                a0 = ffma2(wv.x, hv.x, a0);
                a1 = ffma2(wv.y, hv.y, a1);
            }
            unsigned long long a = addf2(a0, a1);
            obase[(size_t)t * O + o] = f2lo(a) + f2hi(a) + arena[OFF_BFC + o];
        }
    }
}

// ---------------------------------------------------------------------------
// Fused wavefront: one CTA (24 warps) per batch row.
//   A (w0-7):   h1[i]  = tanh(xp0[i] + Whh0·h1[i-1])          (step i at iter i)
//   C (w8-23):  h2[s]  = tanh(Wih1·h1[s] + Whh1·h2[s-1] + b)  (s = i-1 at iter i)
//   FC bursts on A warps every 16 iters from h2 history; xp0 via cp.async.
// ---------------------------------------------------------------------------
__global__ __launch_bounds__(NTH, 1) void fused_kernel(
    const float* __restrict__ xp0,
    const float* __restrict__ Whh0,
    const float* __restrict__ Wih1,
    const float* __restrict__ Whh1,
    const float* __restrict__ b_ih1,
    const float* __restrict__ b_hh1,
    const float* __restrict__ Wfc,
    const float* __restrict__ bfc,
    const int* __restrict__ lengths,
    float* __restrict__ out)
{
    __shared__ __align__(16) float arena[ARENA_F];
    const int b    = blockIdx.x;
    const int tid  = threadIdx.x;
    const int lane = tid & 31;
    const int w    = tid >> 5;
    const int len  = lengths[b];
    const bool isA = (w < 8);

    // stage Wfc (padded to 132-float rows) + b_fc; zero rings
    for (int idx = tid; idx < O * H; idx += NTH)
        arena[OFF_WFC + (idx >> 7) * 132 + (idx & 127)] = Wfc[idx];
    if (tid < O) arena[OFF_BFC + tid] = bfc[tid];
    if (tid < H) {
        arena[OFF_H1 + 128 + tid]      = 0.0f;   // h1[-1]
        arena[OFF_H2 + 31 * 128 + tid] = 0.0f;   // h2[-1]
    }

    // per-thread weights in registers (64 regs)
    unsigned long long wq[32];
    int j, sel4;
    float bias = 0.0f;
    if (isA) {
        j    = w * 16 + (lane >> 1);
        sel4 = (lane & 1) * 4;
        const float* wr = Whh0 + (size_t)j * H + sel4;
#pragma unroll
        for (int ic = 0; ic < 16; ++ic) {
            ulonglong2 v = *(const ulonglong2*)(wr + 8 * ic);
            wq[2 * ic] = v.x; wq[2 * ic + 1] = v.y;
        }
    } else {
        const int wc = w - 8;                 // 0..15
        j = wc * 8 + (lane & 7);
        const int q = lane >> 3;              // quarter of concat-k (0,1: Wih1; 2,3: Whh1)
        sel4 = (q & 1) * 4;
        const float* wr = ((q < 2) ? Wih1 : Whh1) + (size_t)j * H + sel4;
#pragma unroll
        for (int ic = 0; ic < 16; ++ic) {
            ulonglong2 v = *(const ulonglong2*)(wr + 8 * ic);
            wq[2 * ic] = v.x; wq[2 * ic + 1] = v.y;
        }
        bias = b_ih1[j] + b_hh1[j];
    }

    // initial xp0 prefetch: tiles 0 and 1 (A threads: one 16B chunk each)
    const float* xbase = xp0 + (size_t)b * T * H;
    if (isA) {
        cp16(&arena[OFF_XS + tid * 4], xbase + tid * 4);
        CP_COMMIT();
        cp16(&arena[OFF_XS + 1024 + tid * 4], xbase + 1024 + tid * 4);
        CP_COMMIT();
        CP_WAIT1();   // tile 0 resident
    }
    __syncthreads();

    float* obase = out + (size_t)b * T * O;

    for (int i = 0; i <= len; ++i) {
        if (isA) {
            if ((i & 15) == 1 && i >= 17)
                fc_tile(arena, obase, i - 17, i - 2, w, lane);
            if (i < len) {
                const float* src = arena + OFF_H1 + ((i + 1) & 1) * 128 + sel4;
                unsigned long long a0 = 0ull, a1 = 0ull;
#pragma unroll
                for (int ic = 0; ic < 16; ++ic) {
                    ulonglong2 hv = *(const ulonglong2*)(src + 8 * ic);
                    a0 = ffma2(wq[2 * ic],     hv.x, a0);
                    a1 = ffma2(wq[2 * ic + 1], hv.y, a1);
                }
                unsigned long long a = addf2(a0, a1);
                float s = f2lo(a) + f2hi(a);
                s += __shfl_xor_sync(0xffffffffu, s, 1);
                if ((lane & 1) == 0) {
                    float xv = arena[OFF_XS + ((i >> 3) & 1) * 1024 + (i & 7) * 128 + j];
                    arena[OFF_H1 + (i & 1) * 128 + j] = tanh_fast(s + xv);
                }
            }
        } else if (i >= 1) {
            const int q = lane >> 3;
            const float* src = ((q < 2)
                ? (arena + OFF_H1 + ((i + 1) & 1) * 128)
                : (arena + OFF_H2 + ((i - 2) & 31) * 128)) + sel4;
            unsigned long long a0 = 0ull, a1 = 0ull;
#pragma unroll
            for (int ic = 0; ic < 16; ++ic) {
                ulonglong2 hv = *(const ulonglong2*)(src + 8 * ic);
                a0 = ffma2(wq[2 * ic],     hv.x, a0);
                a1 = ffma2(wq[2 * ic + 1], hv.y, a1);
            }
            unsigned long long a = addf2(a0, a1);
            float s = f2lo(a) + f2hi(a);
            s += __shfl_xor_sync(0xffffffffu, s, 8);
            s += __shfl_xor_sync(0xffffffffu, s, 16);
            if (q == 0)
                arena[OFF_H2 + ((i - 1) & 31) * 128 + j] = tanh_fast(s + bias);
        }

        const bool bdry = ((i & 7) == 7) && (i + 1 < len);
        __syncthreads();
        if (bdry) {
            if (isA) {
                int nt = (i >> 3) + 2;
                if (nt < T / XTILE)
                    cp16(&arena[OFF_XS + (nt & 1) * 1024 + tid * 4],
                         xbase + (size_t)nt * 1024 + tid * 4);
                CP_COMMIT();
                CP_WAIT1();   // next tile resident
            }
            __syncthreads();
        }
    }

    // FC cleanup: remaining steps [16*floor((len-1)/16), len-1]
    if (isA) {
        int sf = ((len - 1) >> 4) << 4;
        fc_tile(arena, obase, sf, len - 1, w, lane);
    }

    // padded rows: out[b, t>=len, :] = b_fc
    {
        float* op = obase + (size_t)len * O;
        const int n4 = (T - len) * (O / 4);
        const float4* bv = (const float4*)&arena[OFF_BFC];
        for (int idx = tid; idx < n4; idx += NTH)
            ((float4*)op)[idx] = bv[idx & 7];
    }
}

// ---------------------------------------------------------------------------
extern "C" void kernel_launch(void* const* d_in, const int* in_sizes, int n_in,
                              void* d_out, int out_size)
{
    const float* x      = (const float*)d_in[0];
    const int*   lens   = (const int*)  d_in[1];
    const float* W_ih0  = (const float*)d_in[2];
    const float* W_hh0  = (const float*)d_in[3];
    const float* b_ih0  = (const float*)d_in[4];
    const float* b_hh0  = (const float*)d_in[5];
    const float* W_ih1  = (const float*)d_in[6];
    const float* W_hh1  = (const float*)d_in[7];
    const float* b_ih1  = (const float*)d_in[8];
    const float* b_hh1  = (const float*)d_in[9];
    const float* W_fc   = (const float*)d_in[10];
    const float* b_fc   = (const float*)d_in[11];
    float* out = (float*)d_out;

    float* s0;
    cudaGetSymbolAddress((void**)&s0, g_s0);

    dim3 pgrid(T / 16, B);
    proj_kernel<D><<<pgrid, 128>>>(x, s0, W_ih0, b_ih0, b_hh0, lens);
    fused_kernel<<<B, NTH>>>(s0, W_hh0, W_ih1, W_hh1,
                             b_ih1, b_hh1, W_fc, b_fc, lens, out);
}